// round 16
// baseline (speedup 1.0000x reference)
#include <cuda_runtime.h>
#include <cstdint>
#include <math.h>

namespace {
constexpr int NV = 512;
constexpr int C  = 256;
constexpr int MT = 64;        // j-rows per tile
constexpr int LDA = 260;      // padded smem stride (floats)
constexpr int LDV = 260;
constexpr int NWARP = 16;
constexpr int THREADS = 512;
constexpr int NTILE = NV / MT;

// smem layout (floats)
constexpr int SM_A   = 0;                    // [MT][LDA]
constexpr int SM_V   = SM_A + MT * LDA;      // 2 x [MT][LDV]  (double-buffered v)
constexpr int SM_N   = SM_V + 2 * MT * LDV;  // [C]
constexpr int SM_BQ  = SM_N + C;             // [C]
constexpr int SM_BK  = SM_BQ + C;            // [C]
constexpr int SM_BV  = SM_BK + C;            // [C]
constexpr int SM_STG = SM_BV + C;            // [64][17]
constexpr int SM_SC  = SM_STG + 64 * 17;     // [64]
constexpr int SM_P   = SM_SC + 64;           // [64]
constexpr int SM_SX  = SM_P + 64;            // [C]
constexpr int SM_RED = SM_SX + C;            // [NWARP]
constexpr int SMEM_FLOATS = SM_RED + NWARP;
constexpr int SMEM_BYTES  = SMEM_FLOATS * 4; // ~205 KB (1 CTA/SM)
}

// Blocked tf32 weights: [mat][n_blk(32)][k_blk(32)][64], 8x8 tile contiguous,
// pair-permuted so lane (qid,qlane) reads its B fragment as one float2.
__device__ float g_wt[3 * C * C];

__device__ __forceinline__ float to_tf32(float x) {
    float y; asm("cvt.rna.tf32.f32 %0, %1;" : "=f"(y) : "f"(x)); return y;
}
__device__ __forceinline__ uint32_t smem_u32(const void* p) {
    uint32_t a;
    asm("{ .reg .u64 t; cvta.to.shared.u64 t, %1; cvt.u32.u64 %0, t; }" : "=r"(a) : "l"(p));
    return a;
}
__device__ __forceinline__ void cp_async16(uint32_t dst, const void* src) {
    asm volatile("cp.async.ca.shared.global [%0], [%1], 16;" :: "r"(dst), "l"(src));
}
#define CP_COMMIT() asm volatile("cp.async.commit_group;" ::: "memory")
#define CP_WAIT0()  asm volatile("cp.async.wait_group 0;" ::: "memory")

__global__ __launch_bounds__(256) void prep_weights(
    const float* __restrict__ Wq, const float* __restrict__ Wk, const float* __restrict__ Wv)
{
    const int id  = blockIdx.x * 256 + threadIdx.x;
    const int row = id >> 5, blk = id & 31;
    const float* src = (blockIdx.y == 0) ? Wq : (blockIdx.y == 1 ? Wk : Wv);
    const float* p = src + (size_t)row * C + blk * 8;
    float4 lo = *reinterpret_cast<const float4*>(p);
    float4 hi = *reinterpret_cast<const float4*>(p + 4);
    float4 o0, o1;   // pair-permuted
    o0.x = to_tf32(lo.x); o0.y = to_tf32(hi.x); o0.z = to_tf32(lo.y); o0.w = to_tf32(hi.y);
    o1.x = to_tf32(lo.z); o1.y = to_tf32(hi.z); o1.z = to_tf32(lo.w); o1.w = to_tf32(hi.w);
    float* dst = g_wt + (size_t)blockIdx.y * C * C
               + ((size_t)(row >> 3) * 32 + blk) * 64 + (row & 7) * 8;
    *reinterpret_cast<float4*>(dst)     = o0;
    *reinterpret_cast<float4*>(dst + 4) = o1;
}

__device__ __forceinline__ void mma8(float c[4], const uint32_t a[4], const uint32_t* b) {
    asm volatile(
        "mma.sync.aligned.m16n8k8.row.col.f32.tf32.tf32.f32 "
        "{%0,%1,%2,%3}, {%4,%5,%6,%7}, {%8,%9}, {%0,%1,%2,%3};"
        : "+f"(c[0]), "+f"(c[1]), "+f"(c[2]), "+f"(c[3])
        : "r"(a[0]), "r"(a[1]), "r"(a[2]), "r"(a[3]), "r"(b[0]), "r"(b[1]));
}
__device__ __forceinline__ void ldsm_x4(uint32_t a[4], uint32_t addr) {
    asm volatile("ldmatrix.sync.aligned.m8n8.x4.shared.b16 {%0,%1,%2,%3}, [%4];"
                 : "=r"(a[0]), "=r"(a[1]), "=r"(a[2]), "=r"(a[3]) : "r"(addr));
}
__device__ __forceinline__ void load_b2(uint32_t* b, const float* __restrict__ p, int kc) {
    const float2 t = *reinterpret_cast<const float2*>(p + kc * 64);
    b[0] = __float_as_uint(t.x);
    b[1] = __float_as_uint(t.y);
}

__global__ __launch_bounds__(THREADS, 1) void fused_kernel(
    const float* __restrict__ nmat, const float* __restrict__ s, const float* __restrict__ v,
    const float* __restrict__ bq, const float* __restrict__ bk, const float* __restrict__ bv,
    float* __restrict__ out)
{
    extern __shared__ float sm[];
    float* sA  = sm + SM_A;
    float* sn  = sm + SM_N;
    float* sbq = sm + SM_BQ;
    float* sbk = sm + SM_BK;
    float* sbv = sm + SM_BV;
    float* stg = sm + SM_STG;
    float* ssc = sm + SM_SC;
    float* sp  = sm + SM_P;
    float* sx  = sm + SM_SX;
    float* red = sm + SM_RED;

    const int i     = blockIdx.x;
    const int tid   = threadIdx.x;
    const int wid   = tid >> 5;
    const int lane  = tid & 31;
    const int qid   = lane >> 2;
    const int qlane = lane & 3;
    const int wc0   = wid * 16;

    const uint32_t aB   = smem_u32(sA);
    const uint32_t vB0  = smem_u32(sm + SM_V);
    const uint32_t aBase = aB + (uint32_t)(((lane & 15) * LDA + ((lane >> 4) << 2)) * 4);

    // blocked-weight lane pointers (n_blk base = wid*2)
    const int boff = qid * 8 + qlane * 2;
    const float* pq0 = g_wt + (size_t)(wid * 2) * 2048 + boff;
    const float* pq1 = pq0 + 2048;
    const float* pk0 = pq0 + 1 * C * C;
    const float* pk1 = pq1 + 1 * C * C;
    const float* pv0 = pq0 + 2 * C * C;
    const float* pv1 = pq1 + 2 * C * C;

    if (tid < C) {
        sn[tid]  = nmat[(size_t)i * C + tid];
        sbq[tid] = bq[tid];
        sbk[tid] = bk[tid];
        sbv[tid] = bv[tid];
    }

    // stage raw s-tile -> sA and v-tile -> sv[buf] via cp.async (8+8 per thread)
    auto stage_tile = [&](int jtn, int buf) {
        const int j0n = jtn * MT;
        const uint32_t vbase = vB0 + (uint32_t)buf * (MT * LDV * 4);
#pragma unroll
        for (int it = 0; it < MT * (C / 4) / THREADS; it++) {
            const int idx = it * THREADS + tid;
            const int j  = idx >> 6;
            const int c4 = (idx & 63) * 4;
            const size_t g = ((size_t)i * NV + j0n + j) * C + c4;
            cp_async16(aB + (uint32_t)((j * LDA + c4) * 4), s + g);
            cp_async16(vbase + (uint32_t)((j * LDV + c4) * 4), v + g);
        }
        CP_COMMIT();
    };

    // in-place transform: sA = tf32(sA_raw * sn * n_j)
    auto transform = [&](int jtn) {
        const int j0n = jtn * MT;
#pragma unroll
        for (int it = 0; it < MT * (C / 4) / THREADS; it++) {
            const int idx = it * THREADS + tid;
            const int j  = idx >> 6;
            const int c4 = (idx & 63) * 4;
            float4 sraw = *reinterpret_cast<float4*>(sA + j * LDA + c4);
            const float4 n4  = __ldg(reinterpret_cast<const float4*>(
                nmat + (size_t)(j0n + j) * C + c4));
            const float4 sn4 = *reinterpret_cast<const float4*>(sn + c4);
            float4 r;
            r.x = to_tf32(sn4.x * n4.x * sraw.x);
            r.y = to_tf32(sn4.y * n4.y * sraw.y);
            r.z = to_tf32(sn4.z * n4.z * sraw.z);
            r.w = to_tf32(sn4.w * n4.w * sraw.w);
            *reinterpret_cast<float4*>(sA + j * LDA + c4) = r;
        }
    };

    float m_run = -1e30f, l_run = 0.0f;
    float xr[4] = {0.f, 0.f, 0.f, 0.f};

    // prologue: stage + transform tile 0
    stage_tile(0, 0);
    CP_WAIT0();
    __syncthreads();
    transform(0);
    __syncthreads();

    for (int jt = 0; jt < NTILE; jt++) {
        const int cur = jt & 1;
        const float* sv = sm + SM_V + cur * (MT * LDV);

        // ── single-pass fused Q+K+V GEMM
        float qacc[4][2][4], kacc[4][2][4], vacc[4][2][4];
#pragma unroll
        for (int mb = 0; mb < 4; mb++)
#pragma unroll
            for (int nb = 0; nb < 2; nb++)
#pragma unroll
                for (int e = 0; e < 4; e++) {
                    qacc[mb][nb][e] = 0.f; kacc[mb][nb][e] = 0.f; vacc[mb][nb][e] = 0.f;
                }
        {
#pragma unroll 2
            for (int kc = 0; kc < 32; kc++) {
                uint32_t bqf[2][2], bkf[2][2], bvf[2][2];
                load_b2(bqf[0], pq0, kc);
                load_b2(bqf[1], pq1, kc);
                load_b2(bkf[0], pk0, kc);
                load_b2(bkf[1], pk1, kc);
                load_b2(bvf[0], pv0, kc);
                load_b2(bvf[1], pv1, kc);
#pragma unroll
                for (int mb = 0; mb < 4; mb++) {
                    uint32_t a[4];
                    ldsm_x4(a, aBase + (uint32_t)((mb * 16 * LDA + kc * 8) * 4));
                    mma8(qacc[mb][0], a, bqf[0]);
                    mma8(qacc[mb][1], a, bqf[1]);
                    mma8(kacc[mb][0], a, bkf[0]);
                    mma8(kacc[mb][1], a, bkf[1]);
                    mma8(vacc[mb][0], a, bvf[0]);
                    mma8(vacc[mb][1], a, bvf[1]);
                }
            }
        }
        __syncthreads();   // all warps done reading sA

        // ── launch next tile's copies (sA raw + other v buffer), fly under epilogues
        if (jt + 1 < NTILE) stage_tile(jt + 1, cur ^ 1);

        // ── scores in-register
        {
            float pr[8];
#pragma unroll
            for (int z = 0; z < 8; z++) pr[z] = 0.f;
#pragma unroll
            for (int nb = 0; nb < 2; nb++) {
                const int c0 = wc0 + nb * 8 + 2 * qlane;
                const float bq0 = sbq[c0], bq1 = sbq[c0 + 1];
                const float bk0 = sbk[c0], bk1 = sbk[c0 + 1];
#pragma unroll
                for (int mb = 0; mb < 4; mb++) {
                    const int r0 = mb * 16 + qid;
                    const float2 va = *reinterpret_cast<const float2*>(sv + r0 * LDV + c0);
                    const float2 vb = *reinterpret_cast<const float2*>(sv + (r0 + 8) * LDV + c0);
                    pr[mb * 2 + 0] += (qacc[mb][nb][0] + bq0) * (kacc[mb][nb][0] + bk0) * va.x * va.x
                                    + (qacc[mb][nb][1] + bq1) * (kacc[mb][nb][1] + bk1) * va.y * va.y;
                    pr[mb * 2 + 1] += (qacc[mb][nb][2] + bq0) * (kacc[mb][nb][2] + bk0) * vb.x * vb.x
                                    + (qacc[mb][nb][3] + bq1) * (kacc[mb][nb][3] + bk1) * vb.y * vb.y;
                }
            }
#pragma unroll
            for (int z = 0; z < 8; z++) {
                pr[z] += __shfl_xor_sync(0xffffffffu, pr[z], 1);
                pr[z] += __shfl_xor_sync(0xffffffffu, pr[z], 2);
            }
            if (qlane == 0) {
#pragma unroll
                for (int mb = 0; mb < 4; mb++) {
                    stg[(mb * 16 + qid) * 17 + wid]     = pr[mb * 2 + 0];
                    stg[(mb * 16 + qid + 8) * 17 + wid] = pr[mb * 2 + 1];
                }
            }
        }
        __syncthreads();

        // row-reduce 16 warp partials -> scores
        {
            const int row = tid >> 3, k8 = tid & 7;
            float ssum = stg[row * 17 + k8] + stg[row * 17 + 8 + k8];
            ssum += __shfl_xor_sync(0xffffffffu, ssum, 1);
            ssum += __shfl_xor_sync(0xffffffffu, ssum, 2);
            ssum += __shfl_xor_sync(0xffffffffu, ssum, 4);
            if (k8 == 0) ssc[row] = ssum * 0.0625f;   // 1/sqrt(256)
        }
        __syncthreads();

        // online softmax (replicated)
        {
            float tm = -1e30f;
#pragma unroll 8
            for (int j = 0; j < MT; j++) tm = fmaxf(tm, ssc[j]);
            const float m_new = fmaxf(m_run, tm);
            const float scl = __expf(m_run - m_new);
            l_run *= scl;
#pragma unroll
            for (int z = 0; z < 4; z++) xr[z] *= scl;
            if (tid < MT) sp[tid] = __expf(ssc[tid] - m_new);
            __syncthreads();
            float ls = 0.0f;
#pragma unroll 8
            for (int j = 0; j < MT; j++) ls += sp[j];
            l_run += ls;
            m_run = m_new;
        }

        // ── V epilogue straight from vacc
        {
#pragma unroll
            for (int nb = 0; nb < 2; nb++) {
                const int c0 = wc0 + nb * 8 + 2 * qlane;
                const float bv0 = sbv[c0], bv1 = sbv[c0 + 1];
                float pc0 = 0.f, pc1 = 0.f;
#pragma unroll
                for (int mb = 0; mb < 4; mb++) {
                    const int r0 = mb * 16 + qid;
                    const float p0 = sp[r0], p1 = sp[r0 + 8];
                    const float2 va = *reinterpret_cast<const float2*>(sv + r0 * LDV + c0);
                    const float2 vb = *reinterpret_cast<const float2*>(sv + (r0 + 8) * LDV + c0);
                    pc0 += p0 * (vacc[mb][nb][0] + bv0) * va.x
                         + p1 * (vacc[mb][nb][2] + bv0) * vb.x;
                    pc1 += p0 * (vacc[mb][nb][1] + bv1) * va.y
                         + p1 * (vacc[mb][nb][3] + bv1) * vb.y;
                }
                pc0 += __shfl_xor_sync(0xffffffffu, pc0, 4);
                pc0 += __shfl_xor_sync(0xffffffffu, pc0, 8);
                pc0 += __shfl_xor_sync(0xffffffffu, pc0, 16);
                pc1 += __shfl_xor_sync(0xffffffffu, pc1, 4);
                pc1 += __shfl_xor_sync(0xffffffffu, pc1, 8);
                pc1 += __shfl_xor_sync(0xffffffffu, pc1, 16);
                xr[nb * 2 + 0] += pc0;
                xr[nb * 2 + 1] += pc1;
            }
        }

        // ── complete next tile: wait copies, transform raw s -> A
        if (jt + 1 < NTILE) {
            CP_WAIT0();
            __syncthreads();
            transform(jt + 1);
            __syncthreads();
        }
    }

    // publish per-warp column results
    if (qid == 0) {
#pragma unroll
        for (int nb = 0; nb < 2; nb++) {
            sx[wc0 + nb * 8 + 2 * qlane]     = xr[nb * 2 + 0];
            sx[wc0 + nb * 8 + 2 * qlane + 1] = xr[nb * 2 + 1];
        }
    }
    __syncthreads();

    // residual + L2 normalize
    float x = 0.0f;
    if (tid < C) x = sx[tid] / l_run + sn[tid];
    float sq = (tid < C) ? x * x : 0.0f;
#pragma unroll
    for (int o = 16; o > 0; o >>= 1) sq += __shfl_xor_sync(0xffffffffu, sq, o);
    if (lane == 0) red[wid] = sq;
    __syncthreads();
    float tot = 0.0f;
#pragma unroll
    for (int w = 0; w < NWARP; w++) tot += red[w];
    if (tid < C) out[(size_t)i * C + tid] = x * rsqrtf(tot);
}

extern "C" void kernel_launch(void* const* d_in, const int* in_sizes, int n_in,
                              void* d_out, int out_size) {
    const float* nmat = (const float*)d_in[0];
    const float* s    = (const float*)d_in[1];
    const float* v    = (const float*)d_in[2];
    const float* Wq   = (const float*)d_in[3];
    const float* bq   = (const float*)d_in[4];
    const float* Wk   = (const float*)d_in[5];
    const float* bk   = (const float*)d_in[6];
    const float* Wv   = (const float*)d_in[7];
    const float* bv   = (const float*)d_in[8];

    prep_weights<<<dim3(32, 3), 256>>>(Wq, Wk, Wv);

    cudaFuncSetAttribute(fused_kernel, cudaFuncAttributeMaxDynamicSharedMemorySize, SMEM_BYTES);
    fused_kernel<<<NV, THREADS, SMEM_BYTES>>>(nmat, s, v, bq, bk, bv, (float*)d_out);
}